// round 8
// baseline (speedup 1.0000x reference)
#include <cuda_runtime.h>
#include <cstdint>

typedef unsigned long long u64;

// ---------------------------------------------------------------------------
// EnrichAttention: projections -> scores -> softmax(dim=1) -> ctx -> concat
// -> GRU(512 steps). fp32 with f32x2 (FFMA2) packed math.
// ---------------------------------------------------------------------------

// scratch layout (floats)
#define OFF_T1 0
#define OFF_A1 4194304      // 16384*256
#define OFF_A2 8388608
#define OFF_M  12582912     // 32*512*512 = 8388608 floats
#define OFF_G  20971520     // 16384*512  = 8388608
#define OFF_XP 29360128     // 16384*768  = 12582912
#define OFF_H  41943040     // 2*256*32   = 16384 (transposed h ping-pong)
#define SCRATCH_FLOATS 41959424

__device__ float    g_scratch[SCRATCH_FLOATS];
__device__ unsigned g_bar;

// ---- f32x2 helpers ---------------------------------------------------------
__device__ __forceinline__ u64 dup2(float x) {
    u64 r; asm("mov.b64 %0, {%1, %1};" : "=l"(r) : "f"(x)); return r;
}
__device__ __forceinline__ void fma2(u64& d, u64 a, u64 b) {
    asm("fma.rn.f32x2 %0, %1, %2, %0;" : "+l"(d) : "l"(a), "l"(b));
}
__device__ __forceinline__ u64 add2(u64 a, u64 b) {
    u64 d; asm("add.rn.f32x2 %0, %1, %2;" : "=l"(d) : "l"(a), "l"(b)); return d;
}
__device__ __forceinline__ float2 unpk(u64 v) {
    float2 f; asm("mov.b64 {%0, %1}, %2;" : "=f"(f.x), "=f"(f.y) : "l"(v)); return f;
}

// ---------------------------------------------------------------------------
// 128x128 tile SGEMM, 256 threads, 8x8 microtile via FFMA2, K-tile 8.
// EPI: 0=none, 1=relu, 2=mul by E[r*eN+c], 3=add bias E[c]
// TRANSB: true -> B is [N,K] (C=A*B^T); false -> B is [K,N] (C=A*B)
// ---------------------------------------------------------------------------
template<int EPI, bool TRANSB>
__global__ void __launch_bounds__(256) sgemm_kernel(
    const float* __restrict__ A, const float* __restrict__ B,
    float* __restrict__ C, int K, int lda, int ldb, int ldc,
    long long sA, long long sB, long long sC,
    const float* __restrict__ E, int eN)
{
    A += (size_t)blockIdx.z * sA;
    B += (size_t)blockIdx.z * sB;
    C += (size_t)blockIdx.z * sC;

    __shared__ __align__(16) u64   As2[8][128];  // a duplicated into both lanes
    __shared__ __align__(16) float Bs[8][128];

    const int tid = threadIdx.x;
    const int tx = tid & 15, ty = tid >> 4;
    const int m0 = blockIdx.y * 128, n0 = blockIdx.x * 128;

    const int lr = tid >> 1;
    const int lk = (tid & 1) * 4;
    const int bk = tid >> 5;
    const int bn = (tid & 31) * 4;

    u64 acc2[8][4];
#pragma unroll
    for (int i = 0; i < 8; i++)
#pragma unroll
        for (int j = 0; j < 4; j++) acc2[i][j] = 0ull;

    for (int k0 = 0; k0 < K; k0 += 8) {
        float4 av = *(const float4*)(A + (size_t)(m0 + lr) * lda + k0 + lk);
        float4 bv;
        if (TRANSB) bv = *(const float4*)(B + (size_t)(n0 + lr) * ldb + k0 + lk);
        else        bv = *(const float4*)(B + (size_t)(k0 + bk) * ldb + n0 + bn);

        __syncthreads();
        As2[lk + 0][lr] = dup2(av.x); As2[lk + 1][lr] = dup2(av.y);
        As2[lk + 2][lr] = dup2(av.z); As2[lk + 3][lr] = dup2(av.w);
        if (TRANSB) {
            Bs[lk + 0][lr] = bv.x; Bs[lk + 1][lr] = bv.y;
            Bs[lk + 2][lr] = bv.z; Bs[lk + 3][lr] = bv.w;
        } else {
            *(float4*)&Bs[bk][bn] = bv;
        }
        __syncthreads();

#pragma unroll
        for (int kk = 0; kk < 8; kk++) {
            u64 a2[8], b2[4];
            *(ulonglong2*)&a2[0] = *(const ulonglong2*)&As2[kk][ty * 8 + 0];
            *(ulonglong2*)&a2[2] = *(const ulonglong2*)&As2[kk][ty * 8 + 2];
            *(ulonglong2*)&a2[4] = *(const ulonglong2*)&As2[kk][ty * 8 + 4];
            *(ulonglong2*)&a2[6] = *(const ulonglong2*)&As2[kk][ty * 8 + 6];
            *(ulonglong2*)&b2[0] = *(const ulonglong2*)&Bs[kk][tx * 8 + 0];
            *(ulonglong2*)&b2[2] = *(const ulonglong2*)&Bs[kk][tx * 8 + 4];
#pragma unroll
            for (int i = 0; i < 8; i++)
#pragma unroll
                for (int j = 0; j < 4; j++) fma2(acc2[i][j], a2[i], b2[j]);
        }
    }

#pragma unroll
    for (int i = 0; i < 8; i++) {
        const int r = m0 + ty * 8 + i;
        float* crow = C + (size_t)r * ldc + n0 + tx * 8;
        float v[8];
#pragma unroll
        for (int j = 0; j < 4; j++) {
            float2 f = unpk(acc2[i][j]);
            v[2 * j] = f.x; v[2 * j + 1] = f.y;
        }
#pragma unroll
        for (int j = 0; j < 8; j++) {
            const int c = n0 + tx * 8 + j;
            if (EPI == 1) v[j] = fmaxf(v[j], 0.f);
            else if (EPI == 2) v[j] *= E[(size_t)r * eN + c];
            else if (EPI == 3) v[j] += E[c];
        }
        *(float4*)crow       = make_float4(v[0], v[1], v[2], v[3]);
        *(float4*)(crow + 4) = make_float4(v[4], v[5], v[6], v[7]);
    }
}

// ---------------------------------------------------------------------------
// Softmax over dim=1 (the i axis) of M[32][512][512]. One thread per (b, j).
// ---------------------------------------------------------------------------
__global__ void softmax_dim1_kernel(float* __restrict__ Mm)
{
    const int idx = blockIdx.x * 256 + threadIdx.x;
    const int b = idx >> 9, c = idx & 511;
    float* p = Mm + (size_t)b * (512 * 512) + c;

    float mx = -1e30f, s = 0.f;
    for (int i = 0; i < 512; i++) {
        const float v = p[(size_t)i * 512];
        const float nm = fmaxf(mx, v);
        s = s * __expf(mx - nm) + __expf(v - nm);
        mx = nm;
    }
    const float inv = 1.f / s;
    for (int i = 0; i < 512; i++) {
        const float v = p[(size_t)i * 512];
        p[(size_t)i * 512] = __expf(v - mx) * inv;
    }
}

__global__ void concat_copy_kernel(const float* __restrict__ x1, float* __restrict__ g)
{
    const int idx = blockIdx.x * 256 + threadIdx.x;
    const int m = idx >> 6;
    const int c4 = (idx & 63) << 2;
    *(float4*)&g[(size_t)m * 512 + c4] = *(const float4*)&x1[(size_t)m * 256 + c4];
}

// ---------------------------------------------------------------------------
// Persistent GRU v2: 128 CTAs x 256 threads. CTA owns 2 hidden indices.
// h kept transposed [k][b] in a global ping-pong buffer; f32x2 math packs
// 2 batches per lane. Tight acquire-poll grid barrier (no nanosleep).
// Thread map: bp = tid&15 (batch pair), hl = (tid>>4)&1, kq = tid>>5 (K/32).
// ---------------------------------------------------------------------------
__device__ __forceinline__ unsigned ld_acq(const unsigned* p) {
    unsigned v;
    asm volatile("ld.acquire.gpu.global.u32 %0, [%1];" : "=r"(v) : "l"(p) : "memory");
    return v;
}
__device__ __forceinline__ void red_rel(unsigned* p) {
    asm volatile("red.release.gpu.global.add.u32 [%0], 1;" :: "l"(p) : "memory");
}
__device__ __forceinline__ void fence_gpu() {
    asm volatile("fence.acq_rel.gpu;" ::: "memory");
}

__global__ void __launch_bounds__(256, 1) gru_kernel(
    const float* __restrict__ xp,    // [32*512][768] (x-proj incl. bih)
    const float* __restrict__ whh,   // [768][256]
    const float* __restrict__ bhh,   // [768]
    float* __restrict__ hbufT,       // [2][256][32] transposed ping-pong
    unsigned* bar,
    float* __restrict__ out)         // [32*512][256]
{
    extern __shared__ __align__(16) unsigned char smem_raw[];
    u64*   hs2  = (u64*)smem_raw;            // [256][16] h pairs (32 KB)
    u64*   wp2  = hs2 + 4096;                // [2][256][4] dup'd weights (16 KB)
    u64*   part = wp2 + 2048;                // [3][2][8][16] partials (6 KB)
    float* bhs  = (float*)(part + 768);      // [2][3]

    const int tid = threadIdx.x;
    const int cta = blockIdx.x;
    const int h0 = cta * 2;

    // weights (duplicated into both f32x2 lanes), biases
    for (int idx = tid; idx < 1536; idx += 256) {
        const int k = idx & 255, rem = idx >> 8;   // rem 0..5
        const int hl = rem & 1, g = rem >> 1;
        wp2[(hl * 256 + k) * 4 + g] = dup2(__ldg(&whh[(size_t)(g * 256 + h0 + hl) * 256 + k]));
    }
    if (tid < 6) bhs[(tid & 1) * 3 + (tid >> 1)] = bhh[(tid >> 1) * 256 + h0 + (tid & 1)];
    // zero own slice of h buffer 0 (transposed layout)
    if (tid < 64) hbufT[(h0 + (tid >> 5)) * 32 + (tid & 31)] = 0.f;
    __syncthreads();
    if (tid == 0) { fence_gpu(); red_rel(bar); }

    const int bp = tid & 15;
    const int hl = (tid >> 4) & 1;
    const int kq = tid >> 5;
    unsigned target = 0;

    for (int t = 0; t < 512; t++) {
        // prefetch xp for this step (finalize warp only; independent of h)
        float xr0, xz0, xn0, xr1, xz1, xn1;
        if (tid < 32) {
            const int fb0 = 2 * (tid & 15);
            const int fhl = tid >> 4;
            const float* p0 = xp + ((size_t)fb0 * 512 + t) * 768 + h0 + fhl;
            const float* p1 = p0 + (size_t)512 * 768;
            xr0 = __ldg(p0); xz0 = __ldg(p0 + 256); xn0 = __ldg(p0 + 512);
            xr1 = __ldg(p1); xz1 = __ldg(p1 + 256); xn1 = __ldg(p1 + 512);
        }

        target += 128;
        if (tid == 0) { while (ld_acq(bar) < target) {} }
        __syncthreads();                                        // S1

        // stage transposed h: 8192 floats, fully coalesced, L2 (bypass L1)
        const float4* src = (const float4*)(hbufT + (size_t)(t & 1) * 8192);
        float4* dst = (float4*)hs2;
#pragma unroll
        for (int i = 0; i < 8; i++)
            dst[tid + i * 256] = __ldcg(&src[tid + i * 256]);
        __syncthreads();                                        // S2

        // partial dots: 3 gates x 2 batches per lane, K-slice of 32
        u64 ar = 0ull, az = 0ull, an = 0ull;
        const u64* wrow = wp2 + (hl * 256 + kq * 32) * 4;
        const u64* hrow = hs2 + (kq * 32) * 16 + bp;
#pragma unroll
        for (int i = 0; i < 32; i++) {
            const u64 h2 = hrow[i * 16];
            ulonglong2 w01 = *(const ulonglong2*)&wrow[i * 4];
            const u64 w2 = wrow[i * 4 + 2];
            fma2(ar, h2, w01.x);
            fma2(az, h2, w01.y);
            fma2(an, h2, w2);
        }
        part[((0 * 2 + hl) * 8 + kq) * 16 + bp] = ar;
        part[((1 * 2 + hl) * 8 + kq) * 16 + bp] = az;
        part[((2 * 2 + hl) * 8 + kq) * 16 + bp] = an;
        __syncthreads();                                        // S3

        if (tid < 32) {
            const int fbp = tid & 15, fhl = tid >> 4;
            u64 hr = part[((0 * 2 + fhl) * 8 + 0) * 16 + fbp];
            u64 hz = part[((1 * 2 + fhl) * 8 + 0) * 16 + fbp];
            u64 hn = part[((2 * 2 + fhl) * 8 + 0) * 16 + fbp];
#pragma unroll
            for (int q = 1; q < 8; q++) {
                hr = add2(hr, part[((0 * 2 + fhl) * 8 + q) * 16 + fbp]);
                hz = add2(hz, part[((1 * 2 + fhl) * 8 + q) * 16 + fbp]);
                hn = add2(hn, part[((2 * 2 + fhl) * 8 + q) * 16 + fbp]);
            }
            const float br = bhs[fhl * 3 + 0], bz = bhs[fhl * 3 + 1], bn = bhs[fhl * 3 + 2];
            float2 fr = unpk(hr), fz = unpk(hz), fn = unpk(hn);
            float2 hp = unpk(hs2[(h0 + fhl) * 16 + fbp]);

            const float r0 = 1.f / (1.f + __expf(-(xr0 + fr.x + br)));
            const float z0 = 1.f / (1.f + __expf(-(xz0 + fz.x + bz)));
            const float n0v = tanhf(xn0 + r0 * (fn.x + bn));
            const float h0v = (1.f - z0) * n0v + z0 * hp.x;

            const float r1 = 1.f / (1.f + __expf(-(xr1 + fr.y + br)));
            const float z1 = 1.f / (1.f + __expf(-(xz1 + fz.y + bz)));
            const float n1v = tanhf(xn1 + r1 * (fn.y + bn));
            const float h1v = (1.f - z1) * n1v + z1 * hp.y;

            float* hnxt = hbufT + (size_t)((t + 1) & 1) * 8192;
            *(float2*)&hnxt[(h0 + fhl) * 32 + 2 * fbp] = make_float2(h0v, h1v);

            const int b0 = 2 * fbp;
            out[((size_t)b0 * 512 + t) * 256 + h0 + fhl] = h0v;
            out[((size_t)(b0 + 1) * 512 + t) * 256 + h0 + fhl] = h1v;
        }
        __syncthreads();                                        // S4
        if (tid == 0) { fence_gpu(); red_rel(bar); }
    }
}

// ---------------------------------------------------------------------------
extern "C" void kernel_launch(void* const* d_in, const int* in_sizes, int n_in,
                              void* d_out, int out_size)
{
    const float* x1  = (const float*)d_in[0];
    const float* x2  = (const float*)d_in[1];
    const float* w1  = (const float*)d_in[2];
    const float* w2  = (const float*)d_in[3];
    const float* Dm  = (const float*)d_in[4];
    const float* Wm  = (const float*)d_in[5];
    const float* wih = (const float*)d_in[6];
    const float* whh = (const float*)d_in[7];
    const float* bih = (const float*)d_in[8];
    const float* bhh = (const float*)d_in[9];
    float* out = (float*)d_out;

    float* scratch = nullptr;
    unsigned* bar = nullptr;
    cudaGetSymbolAddress((void**)&scratch, g_scratch);
    cudaGetSymbolAddress((void**)&bar, g_bar);
    cudaMemsetAsync(bar, 0, sizeof(unsigned));

    float* T1 = scratch + OFF_T1;
    float* A1 = scratch + OFF_A1;
    float* A2 = scratch + OFF_A2;
    float* MM = scratch + OFF_M;
    float* GG = scratch + OFF_G;
    float* XP = scratch + OFF_XP;
    float* HH = scratch + OFF_H;

    const dim3 blk(256);
    const int GRU_SMEM = 56 * 1024;
    cudaFuncSetAttribute(gru_kernel, cudaFuncAttributeMaxDynamicSharedMemorySize, GRU_SMEM);

    // t1 = relu(x1 @ w1^T)   [16384,256]
    sgemm_kernel<1, true><<<dim3(2, 128, 1), blk>>>(
        x1, w1, T1, 256, 256, 256, 256, 0, 0, 0, nullptr, 0);
    // a2 = relu(x2 @ w2^T)
    sgemm_kernel<1, true><<<dim3(2, 128, 1), blk>>>(
        x2, w2, A2, 256, 256, 256, 256, 0, 0, 0, nullptr, 0);
    // a1 = t1 @ D
    sgemm_kernel<0, false><<<dim3(2, 128, 1), blk>>>(
        T1, Dm, A1, 256, 256, 256, 256, 0, 0, 0, nullptr, 0);
    // M[b] = (a1[b] @ a2[b]^T) * W      [32][512][512]
    sgemm_kernel<2, true><<<dim3(4, 4, 32), blk>>>(
        A1, A2, MM, 256, 256, 256, 512,
        (long long)512 * 256, (long long)512 * 256, (long long)512 * 512, Wm, 512);
    // softmax over dim=1
    softmax_dim1_kernel<<<64, 256>>>(MM);
    // g left half <- x1
    concat_copy_kernel<<<4096, 256>>>(x1, GG);
    // ctx[b] = M[b] @ x2[b]  -> g right half
    sgemm_kernel<0, false><<<dim3(2, 4, 32), blk>>>(
        MM, x2, GG + 256, 512, 512, 256, 512,
        (long long)512 * 512, (long long)512 * 256, (long long)512 * 512, nullptr, 0);
    // xp = g @ wih^T + bih   [16384][768]
    sgemm_kernel<3, true><<<dim3(6, 128, 1), blk>>>(
        GG, wih, XP, 512, 512, 512, 768, 0, 0, 0, bih, 0);
    // GRU recurrence
    gru_kernel<<<128, 256, GRU_SMEM>>>(XP, whh, bhh, HH, bar, out);
}

// round 9
// speedup vs baseline: 1.2563x; 1.2563x over previous
#include <cuda_runtime.h>
#include <cstdint>

typedef unsigned long long u64;
typedef unsigned int u32;

// ---------------------------------------------------------------------------
// EnrichAttention: projections -> scores -> softmax(dim=1) -> ctx -> concat
// -> GRU(512 steps, cluster-local recurrence).
// ---------------------------------------------------------------------------

// scratch layout (floats)
#define OFF_T1 0
#define OFF_A1 4194304      // 16384*256
#define OFF_A2 8388608
#define OFF_M  12582912     // 32*512*512 = 8388608 floats
#define OFF_G  20971520     // 16384*512  = 8388608
#define OFF_XP 29360128     // 16384*768  = 12582912
#define SCRATCH_FLOATS 41943040

__device__ float g_scratch[SCRATCH_FLOATS];

// ---------------------------------------------------------------------------
// 128x128 tile SGEMM (scalar FFMA version — measured at issue ceiling in R6).
// EPI: 0=none, 1=relu, 2=mul by E[r*eN+c], 3=add bias E[c]
// TRANSB: true -> B is [N,K] (C=A*B^T); false -> B is [K,N] (C=A*B)
// ---------------------------------------------------------------------------
template<int EPI, bool TRANSB>
__global__ void __launch_bounds__(256) sgemm_kernel(
    const float* __restrict__ A, const float* __restrict__ B,
    float* __restrict__ C, int K, int lda, int ldb, int ldc,
    long long sA, long long sB, long long sC,
    const float* __restrict__ E, int eN)
{
    A += (size_t)blockIdx.z * sA;
    B += (size_t)blockIdx.z * sB;
    C += (size_t)blockIdx.z * sC;

    __shared__ float As[8][128];
    __shared__ float Bs[8][128];

    const int tid = threadIdx.x;
    const int tx = tid & 15, ty = tid >> 4;
    const int m0 = blockIdx.y * 128, n0 = blockIdx.x * 128;

    const int lr = tid >> 1;
    const int lk = (tid & 1) * 4;
    const int bk = tid >> 5;
    const int bn = (tid & 31) * 4;

    float acc[8][8];
#pragma unroll
    for (int i = 0; i < 8; i++)
#pragma unroll
        for (int j = 0; j < 8; j++) acc[i][j] = 0.f;

    for (int k0 = 0; k0 < K; k0 += 8) {
        float4 av = *(const float4*)(A + (size_t)(m0 + lr) * lda + k0 + lk);
        float4 bv;
        if (TRANSB) bv = *(const float4*)(B + (size_t)(n0 + lr) * ldb + k0 + lk);
        else        bv = *(const float4*)(B + (size_t)(k0 + bk) * ldb + n0 + bn);

        __syncthreads();
        As[lk + 0][lr] = av.x; As[lk + 1][lr] = av.y;
        As[lk + 2][lr] = av.z; As[lk + 3][lr] = av.w;
        if (TRANSB) {
            Bs[lk + 0][lr] = bv.x; Bs[lk + 1][lr] = bv.y;
            Bs[lk + 2][lr] = bv.z; Bs[lk + 3][lr] = bv.w;
        } else {
            *(float4*)&Bs[bk][bn] = bv;
        }
        __syncthreads();

#pragma unroll
        for (int kk = 0; kk < 8; kk++) {
            float a[8], b[8];
            *(float4*)&a[0] = *(const float4*)&As[kk][ty * 8];
            *(float4*)&a[4] = *(const float4*)&As[kk][ty * 8 + 4];
            *(float4*)&b[0] = *(const float4*)&Bs[kk][tx * 8];
            *(float4*)&b[4] = *(const float4*)&Bs[kk][tx * 8 + 4];
#pragma unroll
            for (int i = 0; i < 8; i++)
#pragma unroll
                for (int j = 0; j < 8; j++) acc[i][j] += a[i] * b[j];
        }
    }

#pragma unroll
    for (int i = 0; i < 8; i++) {
        const int r = m0 + ty * 8 + i;
        float* crow = C + (size_t)r * ldc + n0 + tx * 8;
        float v[8];
#pragma unroll
        for (int j = 0; j < 8; j++) {
            float x = acc[i][j];
            const int c = n0 + tx * 8 + j;
            if (EPI == 1) x = fmaxf(x, 0.f);
            else if (EPI == 2) x *= E[(size_t)r * eN + c];
            else if (EPI == 3) x += E[c];
            v[j] = x;
        }
        *(float4*)crow       = make_float4(v[0], v[1], v[2], v[3]);
        *(float4*)(crow + 4) = make_float4(v[4], v[5], v[6], v[7]);
    }
}

// ---------------------------------------------------------------------------
// Softmax over dim=1 of M[32][512][512]. One thread per (b, j).
// ---------------------------------------------------------------------------
__global__ void softmax_dim1_kernel(float* __restrict__ Mm)
{
    const int idx = blockIdx.x * 256 + threadIdx.x;
    const int b = idx >> 9, c = idx & 511;
    float* p = Mm + (size_t)b * (512 * 512) + c;

    float mx = -1e30f, s = 0.f;
    for (int i = 0; i < 512; i++) {
        const float v = p[(size_t)i * 512];
        const float nm = fmaxf(mx, v);
        s = s * __expf(mx - nm) + __expf(v - nm);
        mx = nm;
    }
    const float inv = 1.f / s;
    for (int i = 0; i < 512; i++) {
        const float v = p[(size_t)i * 512];
        p[(size_t)i * 512] = __expf(v - mx) * inv;
    }
}

__global__ void concat_copy_kernel(const float* __restrict__ x1, float* __restrict__ g)
{
    const int idx = blockIdx.x * 256 + threadIdx.x;
    const int m = idx >> 6;
    const int c4 = (idx & 63) << 2;
    *(float4*)&g[(size_t)m * 512 + c4] = *(const float4*)&x1[(size_t)m * 256 + c4];
}

// ---------------------------------------------------------------------------
// GRU v3: 16 independent clusters of 8 CTAs. Cluster (j) owns batches
// {2j, 2j+1}; CTA rank gi within the cluster owns h-indices [32gi, 32gi+32).
// Weights in registers as f32x2 k-pairs (no dup needed: lanes = even/odd k).
// h exchanged via DSMEM stores + barrier.cluster arrive/wait each step.
// ---------------------------------------------------------------------------
__device__ __forceinline__ u64 pk2(float a, float b) {
    u64 r; asm("mov.b64 %0, {%1, %2};" : "=l"(r) : "f"(a), "f"(b)); return r;
}
__device__ __forceinline__ void fma2(u64& d, u64 a, u64 b) {
    asm("fma.rn.f32x2 %0, %1, %2, %0;" : "+l"(d) : "l"(a), "l"(b));
}
__device__ __forceinline__ u64 add2(u64 a, u64 b) {
    u64 d; asm("add.rn.f32x2 %0, %1, %2;" : "=l"(d) : "l"(a), "l"(b)); return d;
}
__device__ __forceinline__ float2 unpk(u64 v) {
    float2 f; asm("mov.b64 {%0, %1}, %2;" : "=f"(f.x), "=f"(f.y) : "l"(v)); return f;
}
__device__ __forceinline__ u32 saddr(const void* p) {
    u32 a;
    asm("{ .reg .u64 t; cvta.to.shared.u64 t, %1; cvt.u32.u64 %0, t; }"
        : "=r"(a) : "l"(p));
    return a;
}

__global__ void __launch_bounds__(256, 1) __cluster_dims__(8, 1, 1)
gru_kernel(const float* __restrict__ xp,    // [32*512][768] (x-proj incl. bih)
           const float* __restrict__ whh,   // [768][256]
           const float* __restrict__ bhh,   // [768]
           float* __restrict__ out)         // [32*512][256]
{
    __shared__ __align__(16) u64 hbuf[2][2][128];     // [pp][batch][k-pair]
    __shared__ __align__(16) u64 parts[3][2][8][32];  // [gate][batch][kq][h_l]

    const int tid = threadIdx.x;
    u32 gi; asm("mov.u32 %0, %%cluster_ctarank;" : "=r"(gi));
    const int b0 = (blockIdx.x >> 3) * 2;
    const int h_l = tid & 31;
    const int kq  = tid >> 5;
    const int hg  = gi * 32 + h_l;

    // Per-thread weights: w2reg[g][kp] = (w[k], w[k+1]) for k = kq*32 + 2*kp.
    u64 w2reg[3][16];
#pragma unroll
    for (int g = 0; g < 3; g++) {
        const float* wr = whh + (size_t)(g * 256 + hg) * 256 + kq * 32;
#pragma unroll
        for (int kp = 0; kp < 16; kp += 2) {
            float4 v = __ldg((const float4*)(wr + kp * 2));
            w2reg[g][kp]     = pk2(v.x, v.y);
            w2reg[g][kp + 1] = pk2(v.z, v.w);
        }
    }

    // Finalize-thread state (tid < 64): biases + DSMEM target addresses.
    float br = 0.f, bz = 0.f, bn = 0.f;
    int b_l = 0, hl2 = 0;
    u32 ds0 = 0, ds1 = 0;
    if (tid < 64) {
        b_l = tid >> 5; hl2 = tid & 31;
        const int hgf = gi * 32 + hl2;
        br = __ldg(&bhh[hgf]);
        bz = __ldg(&bhh[256 + hgf]);
        bn = __ldg(&bhh[512 + hgf]);
        ds0 = saddr(&((float*)&hbuf[0][b_l][0])[hgf]);
        ds1 = saddr(&((float*)&hbuf[1][b_l][0])[hgf]);
    }

    // h(0) = 0 in local buffer 0
    ((u64*)hbuf)[tid] = 0ull;
    __syncthreads();

    for (int t = 0; t < 512; t++) {
        // prefetch xp (independent of h; overlaps barrier wait)
        float xr = 0.f, xz = 0.f, xn = 0.f;
        if (tid < 64) {
            const float* p = xp + ((size_t)(b0 + b_l) * 512 + t) * 768 + gi * 32 + hl2;
            xr = __ldg(p); xz = __ldg(p + 256); xn = __ldg(p + 512);
        }

        if (t) asm volatile("barrier.cluster.wait.aligned;" ::: "memory");

        // partial dots: uniform-per-warp h broadcasts, weights from registers
        const u64* h0p = &hbuf[t & 1][0][kq * 16];
        const u64* h1p = &hbuf[t & 1][1][kq * 16];
        u64 a00 = 0, a01 = 0, a10 = 0, a11 = 0, a20 = 0, a21 = 0;
#pragma unroll
        for (int kp = 0; kp < 16; kp++) {
            const u64 ha = h0p[kp], hb = h1p[kp];
            fma2(a00, ha, w2reg[0][kp]); fma2(a01, hb, w2reg[0][kp]);
            fma2(a10, ha, w2reg[1][kp]); fma2(a11, hb, w2reg[1][kp]);
            fma2(a20, ha, w2reg[2][kp]); fma2(a21, hb, w2reg[2][kp]);
        }
        parts[0][0][kq][h_l] = a00; parts[0][1][kq][h_l] = a01;
        parts[1][0][kq][h_l] = a10; parts[1][1][kq][h_l] = a11;
        parts[2][0][kq][h_l] = a20; parts[2][1][kq][h_l] = a21;
        __syncthreads();

        if (tid < 64) {
            u64 sr = parts[0][b_l][0][hl2];
            u64 sz = parts[1][b_l][0][hl2];
            u64 sn = parts[2][b_l][0][hl2];
#pragma unroll
            for (int q = 1; q < 8; q++) {
                sr = add2(sr, parts[0][b_l][q][hl2]);
                sz = add2(sz, parts[1][b_l][q][hl2]);
                sn = add2(sn, parts[2][b_l][q][hl2]);
            }
            const float2 fr = unpk(sr), fz = unpk(sz), fn = unpk(sn);
            const float hr = fr.x + fr.y + br;
            const float hz = fz.x + fz.y + bz;
            const float hn = fn.x + fn.y + bn;

            const float r = 1.f / (1.f + __expf(-(xr + hr)));
            const float z = 1.f / (1.f + __expf(-(xz + hz)));
            const float n = tanhf(xn + r * hn);
            const float hp = ((const float*)&hbuf[t & 1][b_l][0])[gi * 32 + hl2];
            const float hnew = (1.f - z) * n + z * hp;

            // broadcast hnew into all 8 cluster CTAs' next-h buffer
            const u32 la = ((t + 1) & 1) ? ds1 : ds0;
#pragma unroll
            for (int rk = 0; rk < 8; rk++) {
                u32 ra;
                asm("mapa.shared::cluster.u32 %0, %1, %2;" : "=r"(ra) : "r"(la), "r"(rk));
                asm volatile("st.shared::cluster.f32 [%0], %1;" :: "r"(ra), "f"(hnew));
            }
            out[((size_t)(b0 + b_l) * 512 + t) * 256 + gi * 32 + hl2] = hnew;
        }
        asm volatile("barrier.cluster.arrive.aligned;" ::: "memory");
    }
    // drain: no CTA may exit while peers still DSMEM-write into it
    asm volatile("barrier.cluster.wait.aligned;" ::: "memory");
}

// ---------------------------------------------------------------------------
extern "C" void kernel_launch(void* const* d_in, const int* in_sizes, int n_in,
                              void* d_out, int out_size)
{
    const float* x1  = (const float*)d_in[0];
    const float* x2  = (const float*)d_in[1];
    const float* w1  = (const float*)d_in[2];
    const float* w2  = (const float*)d_in[3];
    const float* Dm  = (const float*)d_in[4];
    const float* Wm  = (const float*)d_in[5];
    const float* wih = (const float*)d_in[6];
    const float* whh = (const float*)d_in[7];
    const float* bih = (const float*)d_in[8];
    const float* bhh = (const float*)d_in[9];
    float* out = (float*)d_out;

    float* scratch = nullptr;
    cudaGetSymbolAddress((void**)&scratch, g_scratch);

    float* T1 = scratch + OFF_T1;
    float* A1 = scratch + OFF_A1;
    float* A2 = scratch + OFF_A2;
    float* MM = scratch + OFF_M;
    float* GG = scratch + OFF_G;
    float* XP = scratch + OFF_XP;

    const dim3 blk(256);

    // t1 = relu(x1 @ w1^T)   [16384,256]
    sgemm_kernel<1, true><<<dim3(2, 128, 1), blk>>>(
        x1, w1, T1, 256, 256, 256, 256, 0, 0, 0, nullptr, 0);
    // a2 = relu(x2 @ w2^T)
    sgemm_kernel<1, true><<<dim3(2, 128, 1), blk>>>(
        x2, w2, A2, 256, 256, 256, 256, 0, 0, 0, nullptr, 0);
    // a1 = t1 @ D
    sgemm_kernel<0, false><<<dim3(2, 128, 1), blk>>>(
        T1, Dm, A1, 256, 256, 256, 256, 0, 0, 0, nullptr, 0);
    // M[b] = (a1[b] @ a2[b]^T) * W      [32][512][512]
    sgemm_kernel<2, true><<<dim3(4, 4, 32), blk>>>(
        A1, A2, MM, 256, 256, 256, 512,
        (long long)512 * 256, (long long)512 * 256, (long long)512 * 512, Wm, 512);
    // softmax over dim=1
    softmax_dim1_kernel<<<64, 256>>>(MM);
    // g left half <- x1
    concat_copy_kernel<<<4096, 256>>>(x1, GG);
    // ctx[b] = M[b] @ x2[b]  -> g right half
    sgemm_kernel<0, false><<<dim3(2, 4, 32), blk>>>(
        MM, x2, GG + 256, 512, 512, 256, 512,
        (long long)512 * 512, (long long)512 * 256, (long long)512 * 512, nullptr, 0);
    // xp = g @ wih^T + bih   [16384][768]
    sgemm_kernel<3, true><<<dim3(6, 128, 1), blk>>>(
        GG, wih, XP, 512, 512, 512, 768, 0, 0, 0, bih, 0);
    // GRU recurrence (16 independent 8-CTA clusters)
    gru_kernel<<<128, 256>>>(XP, whh, bhh, out);
}

// round 10
// speedup vs baseline: 1.6567x; 1.3187x over previous
#include <cuda_runtime.h>
#include <cstdint>

typedef unsigned long long u64;
typedef unsigned int u32;

// ---------------------------------------------------------------------------
// EnrichAttention: projections -> scores -> softmax(dim=1) -> ctx -> concat
// -> GRU(512 steps, cluster-local recurrence, st.async data-driven sync).
// ---------------------------------------------------------------------------

// scratch layout (floats)
#define OFF_T1 0
#define OFF_A1 4194304      // 16384*256
#define OFF_A2 8388608
#define OFF_M  12582912     // 32*512*512 = 8388608 floats
#define OFF_G  20971520     // 16384*512  = 8388608
#define OFF_XP 29360128     // 16384*768  = 12582912
#define SCRATCH_FLOATS 41943040

__device__ float g_scratch[SCRATCH_FLOATS];

// ---------------------------------------------------------------------------
// 128x128 tile SGEMM (scalar FFMA — measured at the fp32 issue ceiling).
// EPI: 0=none, 1=relu, 2=mul by E[r*eN+c], 3=add bias E[c]
// TRANSB: true -> B is [N,K] (C=A*B^T); false -> B is [K,N] (C=A*B)
// ---------------------------------------------------------------------------
template<int EPI, bool TRANSB>
__global__ void __launch_bounds__(256) sgemm_kernel(
    const float* __restrict__ A, const float* __restrict__ B,
    float* __restrict__ C, int K, int lda, int ldb, int ldc,
    long long sA, long long sB, long long sC,
    const float* __restrict__ E, int eN)
{
    A += (size_t)blockIdx.z * sA;
    B += (size_t)blockIdx.z * sB;
    C += (size_t)blockIdx.z * sC;

    __shared__ float As[8][128];
    __shared__ float Bs[8][128];

    const int tid = threadIdx.x;
    const int tx = tid & 15, ty = tid >> 4;
    const int m0 = blockIdx.y * 128, n0 = blockIdx.x * 128;

    const int lr = tid >> 1;
    const int lk = (tid & 1) * 4;
    const int bk = tid >> 5;
    const int bn = (tid & 31) * 4;

    float acc[8][8];
#pragma unroll
    for (int i = 0; i < 8; i++)
#pragma unroll
        for (int j = 0; j < 8; j++) acc[i][j] = 0.f;

    for (int k0 = 0; k0 < K; k0 += 8) {
        float4 av = *(const float4*)(A + (size_t)(m0 + lr) * lda + k0 + lk);
        float4 bv;
        if (TRANSB) bv = *(const float4*)(B + (size_t)(n0 + lr) * ldb + k0 + lk);
        else        bv = *(const float4*)(B + (size_t)(k0 + bk) * ldb + n0 + bn);

        __syncthreads();
        As[lk + 0][lr] = av.x; As[lk + 1][lr] = av.y;
        As[lk + 2][lr] = av.z; As[lk + 3][lr] = av.w;
        if (TRANSB) {
            Bs[lk + 0][lr] = bv.x; Bs[lk + 1][lr] = bv.y;
            Bs[lk + 2][lr] = bv.z; Bs[lk + 3][lr] = bv.w;
        } else {
            *(float4*)&Bs[bk][bn] = bv;
        }
        __syncthreads();

#pragma unroll
        for (int kk = 0; kk < 8; kk++) {
            float a[8], b[8];
            *(float4*)&a[0] = *(const float4*)&As[kk][ty * 8];
            *(float4*)&a[4] = *(const float4*)&As[kk][ty * 8 + 4];
            *(float4*)&b[0] = *(const float4*)&Bs[kk][tx * 8];
            *(float4*)&b[4] = *(const float4*)&Bs[kk][tx * 8 + 4];
#pragma unroll
            for (int i = 0; i < 8; i++)
#pragma unroll
                for (int j = 0; j < 8; j++) acc[i][j] += a[i] * b[j];
        }
    }

#pragma unroll
    for (int i = 0; i < 8; i++) {
        const int r = m0 + ty * 8 + i;
        float* crow = C + (size_t)r * ldc + n0 + tx * 8;
        float v[8];
#pragma unroll
        for (int j = 0; j < 8; j++) {
            float x = acc[i][j];
            const int c = n0 + tx * 8 + j;
            if (EPI == 1) x = fmaxf(x, 0.f);
            else if (EPI == 2) x *= E[(size_t)r * eN + c];
            else if (EPI == 3) x += E[c];
            v[j] = x;
        }
        *(float4*)crow       = make_float4(v[0], v[1], v[2], v[3]);
        *(float4*)(crow + 4) = make_float4(v[4], v[5], v[6], v[7]);
    }
}

// ---------------------------------------------------------------------------
// Softmax over dim=1 of M[32][512][512]. One thread per (b, j).
// ---------------------------------------------------------------------------
__global__ void softmax_dim1_kernel(float* __restrict__ Mm)
{
    const int idx = blockIdx.x * 256 + threadIdx.x;
    const int b = idx >> 9, c = idx & 511;
    float* p = Mm + (size_t)b * (512 * 512) + c;

    float mx = -1e30f, s = 0.f;
    for (int i = 0; i < 512; i++) {
        const float v = p[(size_t)i * 512];
        const float nm = fmaxf(mx, v);
        s = s * __expf(mx - nm) + __expf(v - nm);
        mx = nm;
    }
    const float inv = 1.f / s;
    for (int i = 0; i < 512; i++) {
        const float v = p[(size_t)i * 512];
        p[(size_t)i * 512] = __expf(v - mx) * inv;
    }
}

__global__ void concat_copy_kernel(const float* __restrict__ x1, float* __restrict__ g)
{
    const int idx = blockIdx.x * 256 + threadIdx.x;
    const int m = idx >> 6;
    const int c4 = (idx & 63) << 2;
    *(float4*)&g[(size_t)m * 512 + c4] = *(const float4*)&x1[(size_t)m * 256 + c4];
}

// ---------------------------------------------------------------------------
// GRU v4: 16 independent clusters of 8 CTAs, data-driven sync.
// Cluster j owns batches {2j,2j+1}; rank gi owns h [32gi,32gi+32).
// h(t+1) broadcast via st.async.shared::cluster with mbarrier complete_tx;
// consumers wait on per-buffer mbarriers (expect 2048 B/phase). No cluster
// barrier in the steady state.
// ---------------------------------------------------------------------------
__device__ __forceinline__ u64 pk2(float a, float b) {
    u64 r; asm("mov.b64 %0, {%1, %2};" : "=l"(r) : "f"(a), "f"(b)); return r;
}
__device__ __forceinline__ void fma2(u64& d, u64 a, u64 b) {
    asm("fma.rn.f32x2 %0, %1, %2, %0;" : "+l"(d) : "l"(a), "l"(b));
}
__device__ __forceinline__ u64 add2(u64 a, u64 b) {
    u64 d; asm("add.rn.f32x2 %0, %1, %2;" : "=l"(d) : "l"(a), "l"(b)); return d;
}
__device__ __forceinline__ float2 unpk(u64 v) {
    float2 f; asm("mov.b64 {%0, %1}, %2;" : "=f"(f.x), "=f"(f.y) : "l"(v)); return f;
}
__device__ __forceinline__ u32 saddr(const void* p) {
    u32 a;
    asm("{ .reg .u64 t; cvta.to.shared.u64 t, %1; cvt.u32.u64 %0, t; }"
        : "=r"(a) : "l"(p));
    return a;
}
__device__ __forceinline__ void mbar_wait(u32 mbar, u32 parity) {
    u32 done;
    asm volatile(
        "{\n\t.reg .pred p;\n\t"
        "mbarrier.try_wait.parity.acquire.cta.shared::cta.b64 p, [%1], %2;\n\t"
        "selp.b32 %0, 1, 0, p;\n\t}"
        : "=r"(done) : "r"(mbar), "r"(parity) : "memory");
    if (!done) {
        asm volatile(
            "{\n\t.reg .pred P1;\n\t"
            "WL%=:\n\t"
            "mbarrier.try_wait.parity.acquire.cta.shared::cta.b64 P1, [%0], %1, 0x989680;\n\t"
            "@P1 bra.uni WD%=;\n\t"
            "bra.uni WL%=;\n\t"
            "WD%=:\n\t}"
            :: "r"(mbar), "r"(parity) : "memory");
    }
}

// One GRU step. CUR = h buffer consumed (t&1). Stores h(t+1) to buffer CUR^1
// of all 8 cluster CTAs via st.async, crediting their mb[CUR^1].
template<int CUR, bool DO_WAIT>
__device__ __forceinline__ void gru_step(
    int t, int tid, int kq, int b0, int gi, int b_l, int hl2,
    const u64 (&w2reg)[3][16],
    u64 (&hbuf)[2][2][128], u64 (&parts)[3][2][8][32],
    u32 mb_cur, u32 parity,
    const u32 (&dd)[8], const u32 (&dm)[8],
    float br, float bz, float bn,
    float& xr_c, float& xz_c, float& xn_c,
    const float* __restrict__ xp, float* __restrict__ out)
{
    // prefetch xp(t+1): full step of latency cover
    float xr_n = 0.f, xz_n = 0.f, xn_n = 0.f;
    if (tid < 64) {
        const int tn = (t + 1 < 512) ? t + 1 : 511;
        const float* p = xp + ((size_t)(b0 + b_l) * 512 + tn) * 768 + gi * 32 + hl2;
        xr_n = __ldg(p); xz_n = __ldg(p + 256); xn_n = __ldg(p + 512);
    }

    if (DO_WAIT) {
        mbar_wait(mb_cur, parity);
        if (tid == 0)   // re-arm this mbarrier for its next phase (t+2)
            asm volatile("mbarrier.arrive.expect_tx.shared.b64 _, [%0], %1;"
                         :: "r"(mb_cur), "r"(2048u) : "memory");
    }

    const int h_l = tid & 31;
    const u64* h0p = &hbuf[CUR][0][kq * 16];
    const u64* h1p = &hbuf[CUR][1][kq * 16];
    u64 a00 = 0, a01 = 0, a10 = 0, a11 = 0, a20 = 0, a21 = 0;
#pragma unroll
    for (int kp = 0; kp < 16; kp++) {
        const u64 ha = h0p[kp], hb = h1p[kp];
        fma2(a00, ha, w2reg[0][kp]); fma2(a01, hb, w2reg[0][kp]);
        fma2(a10, ha, w2reg[1][kp]); fma2(a11, hb, w2reg[1][kp]);
        fma2(a20, ha, w2reg[2][kp]); fma2(a21, hb, w2reg[2][kp]);
    }
    parts[0][0][kq][h_l] = a00; parts[0][1][kq][h_l] = a01;
    parts[1][0][kq][h_l] = a10; parts[1][1][kq][h_l] = a11;
    parts[2][0][kq][h_l] = a20; parts[2][1][kq][h_l] = a21;
    __syncthreads();

    if (tid < 64) {
        u64 sr = parts[0][b_l][0][hl2];
        u64 sz = parts[1][b_l][0][hl2];
        u64 sn = parts[2][b_l][0][hl2];
#pragma unroll
        for (int q = 1; q < 8; q++) {
            sr = add2(sr, parts[0][b_l][q][hl2]);
            sz = add2(sz, parts[1][b_l][q][hl2]);
            sn = add2(sn, parts[2][b_l][q][hl2]);
        }
        const float2 fr = unpk(sr), fz = unpk(sz), fn = unpk(sn);
        const float hr = fr.x + fr.y + br;
        const float hz = fz.x + fz.y + bz;
        const float hn = fn.x + fn.y + bn;

        const float r = 1.f / (1.f + __expf(-(xr_c + hr)));
        const float z = 1.f / (1.f + __expf(-(xz_c + hz)));
        const float n = tanhf(xn_c + r * hn);
        const float hp = ((const float*)&hbuf[CUR][b_l][0])[gi * 32 + hl2];
        const float hnew = (1.f - z) * n + z * hp;
        const u32 hbits = __float_as_uint(hnew);

        // broadcast hnew + tx credit to all 8 cluster CTAs (critical path first)
#pragma unroll
        for (int rk = 0; rk < 8; rk++)
            asm volatile(
                "st.async.shared::cluster.mbarrier::complete_tx::bytes.b32 [%0], %1, [%2];"
                :: "r"(dd[rk]), "r"(hbits), "r"(dm[rk]) : "memory");

        out[((size_t)(b0 + b_l) * 512 + t) * 256 + gi * 32 + hl2] = hnew;
    }
    xr_c = xr_n; xz_c = xz_n; xn_c = xn_n;
}

__global__ void __launch_bounds__(256, 1) __cluster_dims__(8, 1, 1)
gru_kernel(const float* __restrict__ xp,    // [32*512][768] (x-proj incl. bih)
           const float* __restrict__ whh,   // [768][256]
           const float* __restrict__ bhh,   // [768]
           float* __restrict__ out)         // [32*512][256]
{
    __shared__ __align__(16) u64 hbuf[2][2][128];     // [pp][batch][k-pair]
    __shared__ __align__(16) u64 parts[3][2][8][32];  // [gate][batch][kq][h_l]
    __shared__ __align__(8)  u64 mbars[2];

    const int tid = threadIdx.x;
    u32 gi; asm("mov.u32 %0, %%cluster_ctarank;" : "=r"(gi));
    const int b0 = (blockIdx.x >> 3) * 2;
    const int h_l = tid & 31;
    const int kq  = tid >> 5;
    const int hg  = gi * 32 + h_l;

    // per-thread weights as f32x2 k-pairs (lanes = even/odd k; no dup needed)
    u64 w2reg[3][16];
#pragma unroll
    for (int g = 0; g < 3; g++) {
        const float* wr = whh + (size_t)(g * 256 + hg) * 256 + kq * 32;
#pragma unroll
        for (int kp = 0; kp < 16; kp += 2) {
            float4 v = __ldg((const float4*)(wr + kp * 2));
            w2reg[g][kp]     = pk2(v.x, v.y);
            w2reg[g][kp + 1] = pk2(v.z, v.w);
        }
    }

    const u32 mb0 = saddr(&mbars[0]);
    const u32 mb1 = saddr(&mbars[1]);
    if (tid == 0) {
        asm volatile("mbarrier.init.shared.b64 [%0], 1;" :: "r"(mb0) : "memory");
        asm volatile("mbarrier.init.shared.b64 [%0], 1;" :: "r"(mb1) : "memory");
        asm volatile("fence.proxy.async.shared::cta;" ::: "memory");
        // arm phase 0 of both (first uses: mb1 at t=1, mb0 at t=2)
        asm volatile("mbarrier.arrive.expect_tx.shared.b64 _, [%0], %1;"
                     :: "r"(mb0), "r"(2048u) : "memory");
        asm volatile("mbarrier.arrive.expect_tx.shared.b64 _, [%0], %1;"
                     :: "r"(mb1), "r"(2048u) : "memory");
    }
    // h(0) = 0
    ((u64*)hbuf)[tid] = 0ull;
    ((u64*)hbuf)[tid + 256] = 0ull;
    __syncthreads();
    // all mbarriers initialized before any peer st.async can arrive
    asm volatile("barrier.cluster.arrive.aligned;" ::: "memory");
    asm volatile("barrier.cluster.wait.aligned;" ::: "memory");

    // finalize-thread state: biases + precomputed DSMEM data/mbar addresses
    float br = 0.f, bz = 0.f, bn = 0.f;
    int b_l = 0, hl2 = 0;
    u32 dd0[8], dd1[8], dm0[8], dm1[8];
#pragma unroll
    for (int rk = 0; rk < 8; rk++) { dd0[rk] = dd1[rk] = dm0[rk] = dm1[rk] = 0u; }
    if (tid < 64) {
        b_l = tid >> 5; hl2 = tid & 31;
        const int hgf = gi * 32 + hl2;
        br = __ldg(&bhh[hgf]);
        bz = __ldg(&bhh[256 + hgf]);
        bn = __ldg(&bhh[512 + hgf]);
        const u32 la0 = saddr(&((float*)&hbuf[0][b_l][0])[hgf]);
        const u32 la1 = saddr(&((float*)&hbuf[1][b_l][0])[hgf]);
#pragma unroll
        for (int rk = 0; rk < 8; rk++) {
            asm("mapa.shared::cluster.u32 %0, %1, %2;" : "=r"(dd0[rk]) : "r"(la0), "r"(rk));
            asm("mapa.shared::cluster.u32 %0, %1, %2;" : "=r"(dd1[rk]) : "r"(la1), "r"(rk));
            asm("mapa.shared::cluster.u32 %0, %1, %2;" : "=r"(dm0[rk]) : "r"(mb0), "r"(rk));
            asm("mapa.shared::cluster.u32 %0, %1, %2;" : "=r"(dm1[rk]) : "r"(mb1), "r"(rk));
        }
    }

    // preload xp(0)
    float xr_c = 0.f, xz_c = 0.f, xn_c = 0.f;
    if (tid < 64) {
        const float* p = xp + ((size_t)(b0 + b_l) * 512) * 768 + gi * 32 + hl2;
        xr_c = __ldg(p); xz_c = __ldg(p + 256); xn_c = __ldg(p + 512);
    }

    u32 p0 = 0, p1 = 0;
    // t=0: local zeros, no wait; writes h(1) -> buf1/mb1
    gru_step<0, false>(0, tid, kq, b0, gi, b_l, hl2, w2reg, hbuf, parts,
                       mb0, 0u, dd1, dm1, br, bz, bn, xr_c, xz_c, xn_c, xp, out);
    for (int t = 1; t < 511; t += 2) {
        gru_step<1, true>(t, tid, kq, b0, gi, b_l, hl2, w2reg, hbuf, parts,
                          mb1, p1, dd0, dm0, br, bz, bn, xr_c, xz_c, xn_c, xp, out);
        p1 ^= 1u;
        gru_step<0, true>(t + 1, tid, kq, b0, gi, b_l, hl2, w2reg, hbuf, parts,
                          mb0, p0, dd1, dm1, br, bz, bn, xr_c, xz_c, xn_c, xp, out);
        p0 ^= 1u;
    }
    gru_step<1, true>(511, tid, kq, b0, gi, b_l, hl2, w2reg, hbuf, parts,
                      mb1, p1, dd0, dm0, br, bz, bn, xr_c, xz_c, xn_c, xp, out);
    // drain: absorb h(512) arrivals into buf0 so no peer stores into a dead CTA
    mbar_wait(mb0, p0);
}

// ---------------------------------------------------------------------------
extern "C" void kernel_launch(void* const* d_in, const int* in_sizes, int n_in,
                              void* d_out, int out_size)
{
    const float* x1  = (const float*)d_in[0];
    const float* x2  = (const float*)d_in[1];
    const float* w1  = (const float*)d_in[2];
    const float* w2  = (const float*)d_in[3];
    const float* Dm  = (const float*)d_in[4];
    const float* Wm  = (const float*)d_in[5];
    const float* wih = (const float*)d_in[6];
    const float* whh = (const float*)d_in[7];
    const float* bih = (const float*)d_in[8];
    const float* bhh = (const float*)d_in[9];
    float* out = (float*)d_out;

    float* scratch = nullptr;
    cudaGetSymbolAddress((void**)&scratch, g_scratch);

    float* T1 = scratch + OFF_T1;
    float* A1 = scratch + OFF_A1;
    float* A2 = scratch + OFF_A2;
    float* MM = scratch + OFF_M;
    float* GG = scratch + OFF_G;
    float* XP = scratch + OFF_XP;

    const dim3 blk(256);

    // t1 = relu(x1 @ w1^T)   [16384,256]
    sgemm_kernel<1, true><<<dim3(2, 128, 1), blk>>>(
        x1, w1, T1, 256, 256, 256, 256, 0, 0, 0, nullptr, 0);
    // a2 = relu(x2 @ w2^T)
    sgemm_kernel<1, true><<<dim3(2, 128, 1), blk>>>(
        x2, w2, A2, 256, 256, 256, 256, 0, 0, 0, nullptr, 0);
    // a1 = t1 @ D
    sgemm_kernel<0, false><<<dim3(2, 128, 1), blk>>>(
        T1, Dm, A1, 256, 256, 256, 256, 0, 0, 0, nullptr, 0);
    // M[b] = (a1[b] @ a2[b]^T) * W      [32][512][512]
    sgemm_kernel<2, true><<<dim3(4, 4, 32), blk>>>(
        A1, A2, MM, 256, 256, 256, 512,
        (long long)512 * 256, (long long)512 * 256, (long long)512 * 512, Wm, 512);
    // softmax over dim=1
    softmax_dim1_kernel<<<64, 256>>>(MM);
    // g left half <- x1
    concat_copy_kernel<<<4096, 256>>>(x1, GG);
    // ctx[b] = M[b] @ x2[b]  -> g right half
    sgemm_kernel<0, false><<<dim3(2, 4, 32), blk>>>(
        MM, x2, GG + 256, 512, 512, 256, 512,
        (long long)512 * 512, (long long)512 * 256, (long long)512 * 512, nullptr, 0);
    // xp = g @ wih^T + bih   [16384][768]
    sgemm_kernel<3, true><<<dim3(6, 128, 1), blk>>>(
        GG, wih, XP, 512, 512, 512, 768, 0, 0, 0, bih, 0);
    // GRU recurrence (16 independent 8-CTA clusters, data-driven sync)
    gru_kernel<<<128, 256>>>(XP, whh, bhh, out);
}

// round 12
// speedup vs baseline: 2.2303x; 1.3462x over previous
#include <cuda_runtime.h>
#include <cuda_bf16.h>
#include <cstdint>

typedef unsigned long long u64;
typedef unsigned int u32;

// ---------------------------------------------------------------------------
// EnrichAttention: bf16x3-split HMMA GEMMs -> softmax(dim=1) -> ctx -> concat
// -> GRU(512 steps, cluster st.async recurrence).
// tcgen05 is NOT available (harness compiles PTX at compute_103, no 'a');
// legacy mma.sync/ldmatrix (HMMA) is.
// ---------------------------------------------------------------------------

// scratch layout (floats)
#define OFF_T1 0
#define OFF_A1 4194304      // 16384*256
#define OFF_A2 8388608
#define OFF_M  12582912     // 32*512*512 = 8388608 floats
#define OFF_G  20971520     // 16384*512  = 8388608
#define OFF_XP 29360128     // 16384*768  = 12582912
#define SCRATCH_FLOATS 41943040

__device__ float g_scratch[SCRATCH_FLOATS];

// ---- helpers ----------------------------------------------------------------
__device__ __forceinline__ u32 saddr(const void* p) {
    u32 a;
    asm("{ .reg .u64 t; cvta.to.shared.u64 t, %1; cvt.u32.u64 %0, t; }"
        : "=r"(a) : "l"(p));
    return a;
}
__device__ __forceinline__ void mbar_wait(u32 mbar, u32 parity) {
    u32 done;
    asm volatile(
        "{\n\t.reg .pred p;\n\t"
        "mbarrier.try_wait.parity.acquire.cta.shared::cta.b64 p, [%1], %2;\n\t"
        "selp.b32 %0, 1, 0, p;\n\t}"
        : "=r"(done) : "r"(mbar), "r"(parity) : "memory");
    if (!done) {
        asm volatile(
            "{\n\t.reg .pred P1;\n\t"
            "WL%=:\n\t"
            "mbarrier.try_wait.parity.acquire.cta.shared::cta.b64 P1, [%0], %1, 0x989680;\n\t"
            "@P1 bra.uni WD%=;\n\t"
            "bra.uni WL%=;\n\t"
            "WD%=:\n\t}"
            :: "r"(mbar), "r"(parity) : "memory");
    }
}

// ---------------------------------------------------------------------------
// bf16x3 HMMA GEMM. CTA tile 128x128, K-tile 32, 256 threads = 8 warps (2x4),
// warp tile 64x32. Double-buffered smem; rows padded to 40 bf16 (80 B).
// Split: x = hi(bf16) + lo(bf16); acc += Ah*Bh + Ah*Bl + Al*Bh  (fp32 acc).
// EPI: 0=none, 1=relu, 2=mul by E[r*eN+c], 3=add bias E[c]
// TRANSB: true -> B is [N,K] (C=A*B^T); false -> B is [K,N] (C=A*B)
// ---------------------------------------------------------------------------
#define LDR 40                       // padded row length (bf16 elems)
#define MAT_ELEMS (128 * LDR)        // 5120 elems per matrix
#define BUF_ELEMS (4 * MAT_ELEMS)    // Ah, Al, Bh, Bl
#define GEMM_SMEM (2 * BUF_ELEMS * 2)  // bytes = 163840

__device__ __forceinline__ void split2(float x, float y, u32& hi, u32& lo) {
    __nv_bfloat16 hx = __float2bfloat16_rn(x), hy = __float2bfloat16_rn(y);
    float rx = x - __bfloat162float(hx), ry = y - __bfloat162float(hy);
    __nv_bfloat16 lx = __float2bfloat16_rn(rx), ly = __float2bfloat16_rn(ry);
    hi = ((u32)__bfloat16_as_ushort(hy) << 16) | __bfloat16_as_ushort(hx);
    lo = ((u32)__bfloat16_as_ushort(ly) << 16) | __bfloat16_as_ushort(lx);
}
__device__ __forceinline__ void ldsm4(u32& r0, u32& r1, u32& r2, u32& r3, u32 a) {
    asm volatile("ldmatrix.sync.aligned.m8n8.x4.shared.b16 {%0,%1,%2,%3}, [%4];"
                 : "=r"(r0), "=r"(r1), "=r"(r2), "=r"(r3) : "r"(a));
}
__device__ __forceinline__ void mma_bf16(float* c, const u32* a, const u32* b) {
    asm volatile(
        "mma.sync.aligned.m16n8k16.row.col.f32.bf16.bf16.f32 "
        "{%0,%1,%2,%3}, {%4,%5,%6,%7}, {%8,%9}, {%0,%1,%2,%3};"
        : "+f"(c[0]), "+f"(c[1]), "+f"(c[2]), "+f"(c[3])
        : "r"(a[0]), "r"(a[1]), "r"(a[2]), "r"(a[3]), "r"(b[0]), "r"(b[1]));
}

template<int EPI, bool TRANSB>
__global__ void __launch_bounds__(256) mma_gemm(
    const float* __restrict__ A, const float* __restrict__ B,
    float* __restrict__ C, int K, int lda, int ldb, int ldc,
    long long sA, long long sB, long long sC,
    const float* __restrict__ E, int eN)
{
    extern __shared__ __align__(16) __nv_bfloat16 sm[];
    A += (size_t)blockIdx.z * sA;
    B += (size_t)blockIdx.z * sB;
    C += (size_t)blockIdx.z * sC;

    const int tid = threadIdx.x;
    const int wid = tid >> 5, lane = tid & 31;
    const int wm = wid >> 2, wn = wid & 3;
    const int m0 = blockIdx.y * 128, n0 = blockIdx.x * 128;

    // loader indices
    const int ar0 = tid >> 3;             // row (A / TRANSB-B), +32/iter
    const int akq = (tid & 7) * 4;        // k quad
    const int nk  = tid & 31;             // NN loader: k
    const int nn4 = (tid >> 5) * 4;       // NN loader: n quad, +32/iter

    // ldmatrix per-thread tile offsets (bf16 elems)
    const int q = lane >> 3, lr = lane & 7;
    const int a_t = (lr + (q & 1) * 8) * LDR + (q >> 1) * 8;
    const int b_t = (lr + (q >> 1) * 8) * LDR + (q & 1) * 8;
    const u32 smb = saddr(sm);

    float acc[4][4][4];
#pragma unroll
    for (int mt = 0; mt < 4; mt++)
#pragma unroll
        for (int nt = 0; nt < 4; nt++)
#pragma unroll
            for (int e = 0; e < 4; e++) acc[mt][nt][e] = 0.f;

    const int nch = K >> 5;

    // ---- prologue: load chunk 0 into buffer 0 ----
    {
        __nv_bfloat16* Ah = sm;
        __nv_bfloat16* Al = sm + MAT_ELEMS;
        __nv_bfloat16* Bh = sm + 2 * MAT_ELEMS;
        __nv_bfloat16* Bl = sm + 3 * MAT_ELEMS;
#pragma unroll
        for (int i = 0; i < 4; i++) {
            const int r = ar0 + i * 32;
            float4 v = *(const float4*)(A + (size_t)(m0 + r) * lda + akq);
            uint2 h, l;
            split2(v.x, v.y, h.x, l.x); split2(v.z, v.w, h.y, l.y);
            *(uint2*)&Ah[r * LDR + akq] = h;
            *(uint2*)&Al[r * LDR + akq] = l;
        }
        if (TRANSB) {
#pragma unroll
            for (int i = 0; i < 4; i++) {
                const int r = ar0 + i * 32;
                float4 v = *(const float4*)(B + (size_t)(n0 + r) * ldb + akq);
                uint2 h, l;
                split2(v.x, v.y, h.x, l.x); split2(v.z, v.w, h.y, l.y);
                *(uint2*)&Bh[r * LDR + akq] = h;
                *(uint2*)&Bl[r * LDR + akq] = l;
            }
        } else {
#pragma unroll
            for (int i = 0; i < 4; i++) {
                const int nb = nn4 + i * 32;
                float4 v = *(const float4*)(B + (size_t)nk * ldb + n0 + nb);
                const float vv[4] = { v.x, v.y, v.z, v.w };
#pragma unroll
                for (int j = 0; j < 4; j++) {
                    __nv_bfloat16 hb = __float2bfloat16_rn(vv[j]);
                    float rres = vv[j] - __bfloat162float(hb);
                    Bh[(nb + j) * LDR + nk] = hb;
                    Bl[(nb + j) * LDR + nk] = __float2bfloat16_rn(rres);
                }
            }
        }
    }
    __syncthreads();

    for (int c = 0; c < nch; c++) {
        const int buf = c & 1;
        const u32 base = smb + buf * (BUF_ELEMS * 2);

        // prefetch chunk c+1 into registers
        float4 apre[4], bpre[4];
        if (c + 1 < nch) {
            const int k0 = (c + 1) * 32;
#pragma unroll
            for (int i = 0; i < 4; i++)
                apre[i] = *(const float4*)(A + (size_t)(m0 + ar0 + i * 32) * lda + k0 + akq);
            if (TRANSB) {
#pragma unroll
                for (int i = 0; i < 4; i++)
                    bpre[i] = *(const float4*)(B + (size_t)(n0 + ar0 + i * 32) * ldb + k0 + akq);
            } else {
#pragma unroll
                for (int i = 0; i < 4; i++)
                    bpre[i] = *(const float4*)(B + (size_t)(k0 + nk) * ldb + n0 + nn4 + i * 32);
            }
        }

        // ---- MMA on buffer buf: 2 k-steps of 16 ----
#pragma unroll
        for (int ks = 0; ks < 32; ks += 16) {
            u32 ah[4][4], al[4][4], bh[4][2], bl[4][2];
#pragma unroll
            for (int mt = 0; mt < 4; mt++) {
                const u32 off = (u32)(a_t + (wm * 64 + mt * 16) * LDR + ks) * 2;
                ldsm4(ah[mt][0], ah[mt][1], ah[mt][2], ah[mt][3], base + off);
                ldsm4(al[mt][0], al[mt][1], al[mt][2], al[mt][3],
                      base + off + MAT_ELEMS * 2);
            }
#pragma unroll
            for (int np = 0; np < 2; np++) {
                const u32 off = (u32)(b_t + (wn * 32 + np * 16) * LDR + ks) * 2;
                u32 t0, t1, t2, t3;
                ldsm4(t0, t1, t2, t3, base + off + 2 * MAT_ELEMS * 2);
                bh[2 * np][0] = t0; bh[2 * np][1] = t1;
                bh[2 * np + 1][0] = t2; bh[2 * np + 1][1] = t3;
                ldsm4(t0, t1, t2, t3, base + off + 3 * MAT_ELEMS * 2);
                bl[2 * np][0] = t0; bl[2 * np][1] = t1;
                bl[2 * np + 1][0] = t2; bl[2 * np + 1][1] = t3;
            }
#pragma unroll
            for (int mt = 0; mt < 4; mt++)
#pragma unroll
                for (int nt = 0; nt < 4; nt++) {
                    mma_bf16(acc[mt][nt], ah[mt], bh[nt]);
                    mma_bf16(acc[mt][nt], ah[mt], bl[nt]);
                    mma_bf16(acc[mt][nt], al[mt], bh[nt]);
                }
        }

        // ---- store prefetched chunk into the other buffer ----
        if (c + 1 < nch) {
            __nv_bfloat16* dst = sm + ((c + 1) & 1) * BUF_ELEMS;
            __nv_bfloat16* Ah = dst;
            __nv_bfloat16* Al = dst + MAT_ELEMS;
            __nv_bfloat16* Bh = dst + 2 * MAT_ELEMS;
            __nv_bfloat16* Bl = dst + 3 * MAT_ELEMS;
#pragma unroll
            for (int i = 0; i < 4; i++) {
                const int r = ar0 + i * 32;
                uint2 h, l;
                split2(apre[i].x, apre[i].y, h.x, l.x);
                split2(apre[i].z, apre[i].w, h.y, l.y);
                *(uint2*)&Ah[r * LDR + akq] = h;
                *(uint2*)&Al[r * LDR + akq] = l;
            }
            if (TRANSB) {
#pragma unroll
                for (int i = 0; i < 4; i++) {
                    const int r = ar0 + i * 32;
                    uint2 h, l;
                    split2(bpre[i].x, bpre[i].y, h.x, l.x);
                    split2(bpre[i].z, bpre[i].w, h.y, l.y);
                    *(uint2*)&Bh[r * LDR + akq] = h;
                    *(uint2*)&Bl[r * LDR + akq] = l;
                }
            } else {
#pragma unroll
                for (int i = 0; i < 4; i++) {
                    const int nb = nn4 + i * 32;
                    const float vv[4] = { bpre[i].x, bpre[i].y, bpre[i].z, bpre[i].w };
#pragma unroll
                    for (int j = 0; j < 4; j++) {
                        __nv_bfloat16 hb = __float2bfloat16_rn(vv[j]);
                        float rres = vv[j] - __bfloat162float(hb);
                        Bh[(nb + j) * LDR + nk] = hb;
                        Bl[(nb + j) * LDR + nk] = __float2bfloat16_rn(rres);
                    }
                }
            }
        }
        __syncthreads();
    }

    // ---- epilogue ----
    const int rbase = m0 + wm * 64 + (lane >> 2);
    const int cbase = n0 + wn * 32 + (lane & 3) * 2;
#pragma unroll
    for (int mt = 0; mt < 4; mt++) {
#pragma unroll
        for (int nt = 0; nt < 4; nt++) {
            const int col = cbase + nt * 8;
#pragma unroll
            for (int half = 0; half < 2; half++) {
                const int r = rbase + mt * 16 + half * 8;
                float v0 = acc[mt][nt][half * 2];
                float v1 = acc[mt][nt][half * 2 + 1];
                if (EPI == 1) { v0 = fmaxf(v0, 0.f); v1 = fmaxf(v1, 0.f); }
                else if (EPI == 2) {
                    const float2 e = *(const float2*)&E[(size_t)r * eN + col];
                    v0 *= e.x; v1 *= e.y;
                } else if (EPI == 3) {
                    const float2 e = *(const float2*)&E[col];
                    v0 += e.x; v1 += e.y;
                }
                *(float2*)&C[(size_t)r * ldc + col] = make_float2(v0, v1);
            }
        }
    }
}

// ---------------------------------------------------------------------------
// Softmax over dim=1 of M[32][512][512]. One thread per (b, j).
// ---------------------------------------------------------------------------
__global__ void softmax_dim1_kernel(float* __restrict__ Mm)
{
    const int idx = blockIdx.x * 256 + threadIdx.x;
    const int b = idx >> 9, c = idx & 511;
    float* p = Mm + (size_t)b * (512 * 512) + c;

    float mx = -1e30f, s = 0.f;
    for (int i = 0; i < 512; i++) {
        const float v = p[(size_t)i * 512];
        const float nm = fmaxf(mx, v);
        s = s * __expf(mx - nm) + __expf(v - nm);
        mx = nm;
    }
    const float inv = 1.f / s;
    for (int i = 0; i < 512; i++) {
        const float v = p[(size_t)i * 512];
        p[(size_t)i * 512] = __expf(v - mx) * inv;
    }
}

__global__ void concat_copy_kernel(const float* __restrict__ x1, float* __restrict__ g)
{
    const int idx = blockIdx.x * 256 + threadIdx.x;
    const int m = idx >> 6;
    const int c4 = (idx & 63) << 2;
    *(float4*)&g[(size_t)m * 512 + c4] = *(const float4*)&x1[(size_t)m * 256 + c4];
}

// ---------------------------------------------------------------------------
// GRU v4 (unchanged): 16 clusters of 8 CTAs, st.async data-driven sync.
// ---------------------------------------------------------------------------
__device__ __forceinline__ u64 pk2(float a, float b) {
    u64 r; asm("mov.b64 %0, {%1, %2};" : "=l"(r) : "f"(a), "f"(b)); return r;
}
__device__ __forceinline__ void fma2(u64& d, u64 a, u64 b) {
    asm("fma.rn.f32x2 %0, %1, %2, %0;" : "+l"(d) : "l"(a), "l"(b));
}
__device__ __forceinline__ u64 add2(u64 a, u64 b) {
    u64 d; asm("add.rn.f32x2 %0, %1, %2;" : "=l"(d) : "l"(a), "l"(b)); return d;
}
__device__ __forceinline__ float2 unpk(u64 v) {
    float2 f; asm("mov.b64 {%0, %1}, %2;" : "=f"(f.x), "=f"(f.y) : "l"(v)); return f;
}

template<int CUR, bool DO_WAIT>
__device__ __forceinline__ void gru_step(
    int t, int tid, int kq, int b0, int gi, int b_l, int hl2,
    const u64 (&w2reg)[3][16],
    u64 (&hbuf)[2][2][128], u64 (&parts)[3][2][8][32],
    u32 mb_cur, u32 parity,
    const u32 (&dd)[8], const u32 (&dm)[8],
    float br, float bz, float bn,
    float& xr_c, float& xz_c, float& xn_c,
    const float* __restrict__ xp, float* __restrict__ out)
{
    float xr_n = 0.f, xz_n = 0.f, xn_n = 0.f;
    if (tid < 64) {
        const int tn = (t + 1 < 512) ? t + 1 : 511;
        const float* p = xp + ((size_t)(b0 + b_l) * 512 + tn) * 768 + gi * 32 + hl2;
        xr_n = __ldg(p); xz_n = __ldg(p + 256); xn_n = __ldg(p + 512);
    }

    if (DO_WAIT) {
        mbar_wait(mb_cur, parity);
        if (tid == 0)
            asm volatile("mbarrier.arrive.expect_tx.shared.b64 _, [%0], %1;"
                         :: "r"(mb_cur), "r"(2048u) : "memory");
    }

    const int h_l = tid & 31;
    const u64* h0p = &hbuf[CUR][0][kq * 16];
    const u64* h1p = &hbuf[CUR][1][kq * 16];
    u64 a00 = 0, a01 = 0, a10 = 0, a11 = 0, a20 = 0, a21 = 0;
#pragma unroll
    for (int kp = 0; kp < 16; kp++) {
        const u64 ha = h0p[kp], hb = h1p[kp];
        fma2(a00, ha, w2reg[0][kp]); fma2(a01, hb, w2reg[0][kp]);
        fma2(a10, ha, w2reg[1][kp]); fma2(a11, hb, w2reg[1][kp]);
        fma2(a20, ha, w2reg[2][kp]); fma2(a21, hb, w2reg[2][kp]);
    }
    parts[0][0][kq][h_l] = a00; parts[0][1][kq][h_l] = a01;
    parts[1][0][kq][h_l] = a10; parts[1][1][kq][h_l] = a11;
    parts[2][0][kq][h_l] = a20; parts[2][1][kq][h_l] = a21;
    __syncthreads();

    if (tid < 64) {
        u64 sr = parts[0][b_l][0][hl2];
        u64 sz = parts[1][b_l][0][hl2];
        u64 sn = parts[2][b_l][0][hl2];
#pragma unroll
        for (int qq = 1; qq < 8; qq++) {
            sr = add2(sr, parts[0][b_l][qq][hl2]);
            sz = add2(sz, parts[1][b_l][qq][hl2]);
            sn = add2(sn, parts[2][b_l][qq][hl2]);
        }
        const float2 fr = unpk(sr), fz = unpk(sz), fn = unpk(sn);
        const float hr = fr.x + fr.y + br;
        const float hz = fz.x + fz.y + bz;
        const float hn = fn.x + fn.y + bn;

        const float r = 1.f / (1.f + __expf(-(xr_c + hr)));
        const float z = 1.f / (1.f + __expf(-(xz_c + hz)));
        const float n = tanhf(xn_c + r * hn);
        const float hp = ((const float*)&hbuf[CUR][b_l][0])[gi * 32 + hl2];
        const float hnew = (1.f - z) * n + z * hp;
        const u32 hbits = __float_as_uint(hnew);

#pragma unroll
        for (int rk = 0; rk < 8; rk++)
            asm volatile(
                "st.async.shared::cluster.mbarrier::complete_tx::bytes.b32 [%0], %1, [%2];"
                :: "r"(dd[rk]), "r"(hbits), "r"(dm[rk]) : "memory");

        out[((size_t)(b0 + b_l) * 512 + t) * 256 + gi * 32 + hl2] = hnew;
    }
    xr_c = xr_n; xz_c = xz_n; xn_c = xn_n;
}

__global__ void __launch_bounds__(256, 1) __cluster_dims__(8, 1, 1)
gru_kernel(const float* __restrict__ xp,
           const float* __restrict__ whh,
           const float* __restrict__ bhh,
           float* __restrict__ out)
{
    __shared__ __align__(16) u64 hbuf[2][2][128];
    __shared__ __align__(16) u64 parts[3][2][8][32];
    __shared__ __align__(8)  u64 mbars[2];

    const int tid = threadIdx.x;
    u32 gi; asm("mov.u32 %0, %%cluster_ctarank;" : "=r"(gi));
    const int b0 = (blockIdx.x >> 3) * 2;
    const int h_l = tid & 31;
    const int kq  = tid >> 5;
    const int hg  = gi * 32 + h_l;

    u64 w2reg[3][16];
#pragma unroll
    for (int g = 0; g < 3; g++) {
        const float* wr = whh + (size_t)(g * 256 + hg) * 256 + kq * 32;
#pragma unroll
        for (int kp = 0; kp < 16; kp += 2) {
            float4 v = __ldg((const float4*)(wr + kp * 2));
            w2reg[g][kp]     = pk2(v.x, v.y);
            w2reg[g][kp + 1] = pk2(v.z, v.w);
        }
    }

    const u32 mb0 = saddr(&mbars[0]);
    const u32 mb1 = saddr(&mbars[1]);
    if (tid == 0) {
        asm volatile("mbarrier.init.shared.b64 [%0], 1;" :: "r"(mb0) : "memory");
        asm volatile("mbarrier.init.shared.b64 [%0], 1;" :: "r"(mb1) : "memory");
        asm volatile("fence.proxy.async.shared::cta;" ::: "memory");
        asm volatile("mbarrier.arrive.expect_tx.shared.b64 _, [%0], %1;"
                     :: "r"(mb0), "r"(2048u) : "memory");
        asm volatile("mbarrier.arrive.expect_tx.shared.b64 _, [%0], %1;"
                     :: "r"(mb1), "r"(2048u) : "memory");
    }
    ((u64*)hbuf)[tid] = 0ull;
    ((u64*)hbuf)[tid + 256] = 0ull;
    __syncthreads();
    asm volatile("barrier.cluster.arrive.aligned;" ::: "memory");
    asm volatile("barrier.cluster.wait.aligned;" ::: "memory");

    float br = 0.f, bz = 0.f, bn = 0.f;
    int b_l = 0, hl2 = 0;
    u32 dd0[8], dd1[8], dm0[8], dm1[8];
#pragma unroll
    for (int rk = 0; rk < 8; rk++) { dd0[rk] = dd1[rk] = dm0[rk] = dm1[rk] = 0u; }
    if (tid < 64) {
        b_l = tid >> 5; hl2 = tid & 31;
        const int hgf = gi * 32 + hl2;
        br = __ldg(&bhh[hgf]);
        bz = __ldg(&bhh[256 + hgf]);
        bn = __ldg(&bhh[512 + hgf]);
        const u32 la0 = saddr(&((float*)&hbuf[0][b_l][0])[hgf]);
        const u32 la1 = saddr(&((float*)&hbuf[1][b_l][0])[hgf]);
#pragma unroll
        for (int rk = 0; rk < 8; rk++) {
            asm("mapa.shared::cluster.u32 %0, %1, %2;" : "=r"(dd0[rk]) : "r"(la0), "r"(rk));
            asm("mapa.shared::cluster.u32 %0, %1, %2;" : "=r"(dd1[rk]) : "r"(la1), "r"(rk));
            asm("mapa.shared::cluster.u32 %0, %1, %2;" : "=r"(dm0[rk]) : "r"(mb0), "r"(rk));
            asm("mapa.shared::cluster.u32 %0, %1, %2;" : "=r"(dm1[rk]) : "r"(mb1), "r"(rk));
        }
    }

    float xr_c = 0.f, xz_c = 0.f, xn_c = 0.f;
    if (tid < 64) {
        const float* p = xp + ((size_t)(b0 + b_l) * 512) * 768 + gi * 32 + hl2;
        xr_c = __ldg(p); xz_c = __ldg(p + 256); xn_c = __ldg(p + 512);
    }

    u32 p0 = 0, p1 = 0;
    gru_step<0, false>(0, tid, kq, b0, gi, b_l, hl2, w2reg, hbuf, parts,
                       mb0, 0u, dd1, dm1, br, bz, bn, xr_c, xz_c, xn_c, xp, out);
    for (int t = 1; t < 511; t += 2) {
        gru_step<1, true>(t, tid, kq, b0, gi, b_l, hl2, w2reg, hbuf, parts,
                          mb1, p1, dd0, dm0, br, bz, bn, xr_c, xz_c, xn_c, xp, out);
        p1 ^= 1u;
        gru_step<0, true>(t + 1, tid, kq, b0, gi, b_l, hl2, w2reg, hbuf, parts,
                          mb0, p0, dd1, dm1, br, bz, bn, xr_c, xz_c, xn_c, xp, out);
        p0 ^= 1u;
    }
    gru_step<1, true>(511, tid, kq, b0, gi, b_l, hl2, w2reg, hbuf, parts,
                      mb1, p1, dd0, dm0, br, bz, bn, xr_c, xz_c, xn_c, xp, out);
    mbar_wait(mb0, p0);
}

// ---------------------------------------------------------------------------
extern "C" void kernel_launch(void* const* d_in, const int* in_sizes, int n_in,
                              void* d_out, int out_size)
{
    const float* x1  = (const float*)d_in[0];
    const float* x2  = (const float*)d_in[1];
    const float* w1  = (const float*)d_in[2];
    const float* w2  = (const float*)d_in[3];
    const float* Dm  = (const float*)d_in[4];
    const float* Wm  = (const float*)d_in[5];
    const float* wih = (const float*)d_in[6];
    const float* whh = (const float*)d_in[7];
    const float* bih = (const float*)d_in[8];
    const float* bhh = (const float*)d_in[9];
    float* out = (float*)d_out;

    float* scratch = nullptr;
    cudaGetSymbolAddress((void**)&scratch, g_scratch);

    float* T1 = scratch + OFF_T1;
    float* A1 = scratch + OFF_A1;
    float* A2 = scratch + OFF_A2;
    float* MM = scratch + OFF_M;
    float* GG = scratch + OFF_G;
    float* XP = scratch + OFF_XP;

    cudaFuncSetAttribute(mma_gemm<1, true>,  cudaFuncAttributeMaxDynamicSharedMemorySize, GEMM_SMEM);
    cudaFuncSetAttribute(mma_gemm<0, false>, cudaFuncAttributeMaxDynamicSharedMemorySize, GEMM_SMEM);
    cudaFuncSetAttribute(mma_gemm<2, true>,  cudaFuncAttributeMaxDynamicSharedMemorySize, GEMM_SMEM);
    cudaFuncSetAttribute(mma_gemm<3, true>,  cudaFuncAttributeMaxDynamicSharedMemorySize, GEMM_SMEM);

    const dim3 blk(256);

    // t1 = relu(x1 @ w1^T)   [16384,256]
    mma_gemm<1, true><<<dim3(2, 128, 1), blk, GEMM_SMEM>>>(
        x1, w1, T1, 256, 256, 256, 256, 0, 0, 0, nullptr, 0);
    // a2 = relu(x2 @ w2^T)
    mma_gemm<1, true><<<dim3(2, 128, 1), blk, GEMM_SMEM>>>(
        x2, w2, A2, 256, 256, 256, 256, 0, 0, 0, nullptr, 0);
    // a1 = t1 @ D
    mma_gemm<0, false><<<dim3(2, 128, 1), blk, GEMM_SMEM>>>(
        T1, Dm, A1, 256, 256, 256, 256, 0, 0, 0, nullptr, 0);
    // M[b] = (a1[b] @ a2[b]^T) * W      [32][512][512]
    mma_gemm<2, true><<<dim3(4, 4, 32), blk, GEMM_SMEM>>>(
        A1, A2, MM, 256, 256, 256, 512,
        (long long)512 * 256, (long long)512 * 256, (long long)512 * 512, Wm, 512);
    // softmax over dim=1
    softmax_dim1_kernel<<<64, 256>>>(MM);
    // g left half <- x1
    concat_copy_kernel<<<4096, 256>>>(x1, GG);
    // ctx[b] = M[b] @ x2[b]  -> g right half
    mma_gemm<0, false><<<dim3(2, 4, 32), blk, GEMM_SMEM>>>(
        MM, x2, GG + 256, 512, 512, 256, 512,
        (long long)512 * 512, (long long)512 * 256, (long long)512 * 512, nullptr, 0);
    // xp = g @ wih^T + bih   [16384][768]
    mma_gemm<3, true><<<dim3(6, 128, 1), blk, GEMM_SMEM>>>(
        GG, wih, XP, 512, 512, 512, 768, 0, 0, 0, bih, 0);
    // GRU recurrence (16 independent 8-CTA clusters, data-driven sync)
    gru_kernel<<<128, 256>>>(XP, whh, bhh, out);
}